// round 1
// baseline (speedup 1.0000x reference)
#include <cuda_runtime.h>
#include <math.h>

#define Bv 4
#define Nv 2048
#define Cv 1024
#define Hv 16
#define Dv 64
#define Mv (Bv*Nv)          // 8192
#define F3 (3*Cv)           // 3072

// ---------------- scratch (static device arrays; no allocation) --------------
__device__ float g_qkv[Mv * F3];           // [M, 3C]   ~100 MB
__device__ float g_q[Bv*Hv*Nv*Dv];         // [B,H,N,D] ~33 MB (pre-scaled by 1/sqrt(D))
__device__ float g_k[Bv*Hv*Nv*Dv];
__device__ float g_v[Bv*Hv*Nv*Dv];
__device__ float g_att[Mv * Cv];           // [B,N,C]   ~33 MB

// ---------------- fp32 NT GEMM: C[m,f] = sum_k A[m,k]*Bw[f,k] (+bias) --------
// BM=BN=128, BK=8, 256 threads, 8x8 per thread.
__global__ __launch_bounds__(256) void sgemm_nt(
    const float* __restrict__ A, const float* __restrict__ Bw,
    float* __restrict__ Cout, int Nn, int K, const float* __restrict__ bias)
{
    __shared__ float As[8][128];
    __shared__ float Bs[8][128];

    const int bm = blockIdx.y, bn = blockIdx.x;
    const int tid = threadIdx.x;
    const int tx = tid & 15, ty = tid >> 4;
    const int lrow = tid >> 1, lcol = (tid & 1) * 4;

    const float* Aload = A  + (size_t)(bm * 128 + lrow) * K + lcol;
    const float* Bload = Bw + (size_t)(bn * 128 + lrow) * K + lcol;

    float acc[8][8];
#pragma unroll
    for (int i = 0; i < 8; i++)
#pragma unroll
        for (int j = 0; j < 8; j++) acc[i][j] = 0.f;

    for (int k0 = 0; k0 < K; k0 += 8) {
        float4 av = *(const float4*)(Aload + k0);
        float4 bv = *(const float4*)(Bload + k0);
        __syncthreads();
        As[lcol + 0][lrow] = av.x; As[lcol + 1][lrow] = av.y;
        As[lcol + 2][lrow] = av.z; As[lcol + 3][lrow] = av.w;
        Bs[lcol + 0][lrow] = bv.x; Bs[lcol + 1][lrow] = bv.y;
        Bs[lcol + 2][lrow] = bv.z; Bs[lcol + 3][lrow] = bv.w;
        __syncthreads();
#pragma unroll
        for (int k = 0; k < 8; k++) {
            float4 a0 = *(const float4*)&As[k][ty * 8];
            float4 a1 = *(const float4*)&As[k][ty * 8 + 4];
            float4 b0 = *(const float4*)&Bs[k][tx * 8];
            float4 b1 = *(const float4*)&Bs[k][tx * 8 + 4];
            float ar[8] = {a0.x, a0.y, a0.z, a0.w, a1.x, a1.y, a1.z, a1.w};
            float br[8] = {b0.x, b0.y, b0.z, b0.w, b1.x, b1.y, b1.z, b1.w};
#pragma unroll
            for (int i = 0; i < 8; i++)
#pragma unroll
                for (int j = 0; j < 8; j++)
                    acc[i][j] = fmaf(ar[i], br[j], acc[i][j]);
        }
    }

    const int row0 = bm * 128 + ty * 8;
    const int col0 = bn * 128 + tx * 8;
#pragma unroll
    for (int i = 0; i < 8; i++) {
        float* outp = Cout + (size_t)(row0 + i) * Nn + col0;
#pragma unroll
        for (int j = 0; j < 8; j++) {
            float vv = acc[i][j];
            if (bias) vv += bias[col0 + j];
            outp[j] = vv;
        }
    }
}

// ---------------- RoPE + transpose to [B,H,N,D] ------------------------------
// One thread handles (b,h,n,dh) for dh in [0,32): computes the rotate_half pair.
__global__ __launch_bounds__(256) void rope_transpose(
    const float* __restrict__ qkv, float* __restrict__ q, float* __restrict__ k,
    float* __restrict__ v, const float* __restrict__ ct, const float* __restrict__ st)
{
    int idx = blockIdx.x * 256 + threadIdx.x;       // [0, B*H*N*32)
    int dh = idx & 31;
    int n  = (idx >> 5) & (Nv - 1);
    int h  = (idx >> 16) & (Hv - 1);
    int b  = idx >> 20;

    size_t base = (size_t)(b * Nv + n) * F3 + h * 64;
    float xq0 = qkv[base + dh],        xq1 = qkv[base + dh + 32];
    float xk0 = qkv[base + Cv + dh],   xk1 = qkv[base + Cv + dh + 32];
    float xv0 = qkv[base + 2*Cv + dh], xv1 = qkv[base + 2*Cv + dh + 32];

    float c0 = ct[n * 64 + dh], c1 = ct[n * 64 + dh + 32];
    float s0 = st[n * 64 + dh], s1 = st[n * 64 + dh + 32];

    const float scale = 0.125f;  // D^-0.5, folded into q
    float q0 = (xq0 * c0 - xq1 * s0) * scale;
    float q1 = (xq1 * c1 + xq0 * s1) * scale;
    float k0 = xk0 * c0 - xk1 * s0;
    float k1 = xk1 * c1 + xk0 * s1;

    size_t obase = (size_t)(idx >> 5) * 64 + dh;    // ((b*H+h)*N+n)*64 + dh
    q[obase] = q0;  q[obase + 32] = q1;
    k[obase] = k0;  k[obase + 32] = k1;
    v[obase] = xv0; v[obase + 32] = xv1;
}

// ---------------- Flash attention, fp32 --------------------------------------
// Block = (b,h, 64-row q tile). 256 threads (16x16), 4x4 micro tiles.
#define SP 65
__global__ __launch_bounds__(256) void attn_kernel(
    const float* __restrict__ q, const float* __restrict__ k,
    const float* __restrict__ v, float* __restrict__ out)
{
    extern __shared__ float sm[];
    float* Qs = sm;                 // [d][i]  64 x 65
    float* Ks = Qs + 64 * SP;       // [d][j]
    float* Ps = Ks + 64 * SP;       // [i][j]
    float* Vs = Ps + 64 * SP;       // [j][d]

    const int bh = blockIdx.y;      // b*16 + h
    const int qt = blockIdx.x;      // q tile (64 rows)
    const float* qb = q + (size_t)bh * Nv * Dv;
    const float* kb = k + (size_t)bh * Nv * Dv;
    const float* vb = v + (size_t)bh * Nv * Dv;

    const int tid = threadIdx.x;
    const int tx = tid & 15, ty = tid >> 4;

    // load Q tile transposed: Qs[d][i]
    for (int t = tid; t < 64 * 64; t += 256) {
        int i = t >> 6, d = t & 63;
        Qs[d * SP + i] = qb[(size_t)(qt * 64 + i) * 64 + d];
    }

    float o[4][4];
    float m[4], l[4];
#pragma unroll
    for (int i = 0; i < 4; i++) {
        m[i] = -3.0e38f; l[i] = 0.f;
#pragma unroll
        for (int j = 0; j < 4; j++) o[i][j] = 0.f;
    }
    __syncthreads();

    for (int kt = 0; kt < Nv / 64; kt++) {
        // load K (transposed) and V tiles
        for (int t = tid; t < 64 * 64; t += 256) {
            int r = t >> 6, d = t & 63;
            Ks[d * SP + r] = kb[(size_t)(kt * 64 + r) * 64 + d];
            Vs[r * SP + d] = vb[(size_t)(kt * 64 + r) * 64 + d];
        }
        __syncthreads();

        // S = Q K^T  (q already scaled)
        float s[4][4];
#pragma unroll
        for (int i = 0; i < 4; i++)
#pragma unroll
            for (int j = 0; j < 4; j++) s[i][j] = 0.f;
#pragma unroll 8
        for (int d = 0; d < 64; d++) {
            float qv[4], kv[4];
#pragma unroll
            for (int i = 0; i < 4; i++) qv[i] = Qs[d * SP + ty * 4 + i];
#pragma unroll
            for (int j = 0; j < 4; j++) kv[j] = Ks[d * SP + tx * 4 + j];
#pragma unroll
            for (int i = 0; i < 4; i++)
#pragma unroll
                for (int j = 0; j < 4; j++)
                    s[i][j] = fmaf(qv[i], kv[j], s[i][j]);
        }

        // online softmax: row reductions across the 16 tx lanes
        float mloc[4], rsum[4];
#pragma unroll
        for (int i = 0; i < 4; i++) {
            float mm = s[i][0];
            mm = fmaxf(mm, s[i][1]); mm = fmaxf(mm, s[i][2]); mm = fmaxf(mm, s[i][3]);
            mloc[i] = mm;
        }
#pragma unroll
        for (int off = 8; off >= 1; off >>= 1)
#pragma unroll
            for (int i = 0; i < 4; i++)
                mloc[i] = fmaxf(mloc[i], __shfl_xor_sync(0xffffffffu, mloc[i], off));

#pragma unroll
        for (int i = 0; i < 4; i++) {
            float mnew = fmaxf(m[i], mloc[i]);
            float alpha = __expf(m[i] - mnew);
            float rs = 0.f;
#pragma unroll
            for (int j = 0; j < 4; j++) {
                float p = __expf(s[i][j] - mnew);
                s[i][j] = p;
                rs += p;
            }
            rsum[i] = rs;
            m[i] = mnew;
            l[i] *= alpha;
#pragma unroll
            for (int j = 0; j < 4; j++) o[i][j] *= alpha;
        }
#pragma unroll
        for (int off = 8; off >= 1; off >>= 1)
#pragma unroll
            for (int i = 0; i < 4; i++)
                rsum[i] += __shfl_xor_sync(0xffffffffu, rsum[i], off);
#pragma unroll
        for (int i = 0; i < 4; i++) l[i] += rsum[i];

        // write P
#pragma unroll
        for (int i = 0; i < 4; i++)
#pragma unroll
            for (int j = 0; j < 4; j++)
                Ps[(ty * 4 + i) * SP + tx * 4 + j] = s[i][j];
        __syncthreads();

        // O += P V
#pragma unroll 8
        for (int jj = 0; jj < 64; jj++) {
            float pv[4], vv[4];
#pragma unroll
            for (int i = 0; i < 4; i++) pv[i] = Ps[(ty * 4 + i) * SP + jj];
#pragma unroll
            for (int j = 0; j < 4; j++) vv[j] = Vs[jj * SP + tx * 4 + j];
#pragma unroll
            for (int i = 0; i < 4; i++)
#pragma unroll
                for (int j = 0; j < 4; j++)
                    o[i][j] = fmaf(pv[i], vv[j], o[i][j]);
        }
        __syncthreads();
    }

    // normalize + write to [B,N,C]
    const int b = bh >> 4, h = bh & 15;
#pragma unroll
    for (int i = 0; i < 4; i++) {
        float inv = 1.0f / l[i];
        int n = qt * 64 + ty * 4 + i;
        float* op = out + (size_t)(b * Nv + n) * Cv + h * 64 + tx * 4;
#pragma unroll
        for (int j = 0; j < 4; j++) op[j] = o[i][j] * inv;
    }
}

// ---------------- launch -----------------------------------------------------
extern "C" void kernel_launch(void* const* d_in, const int* in_sizes, int n_in,
                              void* d_out, int out_size)
{
    const float* x        = (const float*)d_in[0];
    const float* rope_cos = (const float*)d_in[1];
    const float* rope_sin = (const float*)d_in[2];
    const float* w_qkv    = (const float*)d_in[3];
    const float* w_proj   = (const float*)d_in[4];
    const float* b_proj   = (const float*)d_in[5];
    float* out = (float*)d_out;

    float *qkv, *q, *k, *v, *att;
    cudaGetSymbolAddress((void**)&qkv, g_qkv);
    cudaGetSymbolAddress((void**)&q,   g_q);
    cudaGetSymbolAddress((void**)&k,   g_k);
    cudaGetSymbolAddress((void**)&v,   g_v);
    cudaGetSymbolAddress((void**)&att, g_att);

    // 1) QKV GEMM: [8192,1024] x [3072,1024]^T -> [8192,3072]
    sgemm_nt<<<dim3(F3 / 128, Mv / 128), 256>>>(x, w_qkv, qkv, F3, Cv, nullptr);

    // 2) RoPE + transpose to [B,H,N,D]
    rope_transpose<<<(Bv * Hv * Nv * 32) / 256, 256>>>(qkv, q, k, v, rope_cos, rope_sin);

    // 3) Flash attention
    const int SMEM = 4 * 64 * SP * (int)sizeof(float);
    cudaFuncSetAttribute(attn_kernel, cudaFuncAttributeMaxDynamicSharedMemorySize, SMEM);
    attn_kernel<<<dim3(Nv / 64, Bv * Hv), 256, SMEM>>>(q, k, v, att);

    // 4) projection + bias: [8192,1024] x [1024,1024]^T -> d_out
    sgemm_nt<<<dim3(Cv / 128, Mv / 128), 256>>>(att, w_proj, out, Cv, Cv, b_proj);
}

// round 3
// speedup vs baseline: 3.0681x; 3.0681x over previous
#include <cuda_runtime.h>
#include <math.h>
#include <stdint.h>

#define Bv 4
#define Nv 2048
#define Cv 1024
#define Hv 16
#define Dv 64
#define Mv (Bv*Nv)          // 8192
#define F3 (3*Cv)           // 3072

// ---------------- scratch (static device arrays; no allocation) --------------
__device__ float g_qkv[Mv * F3];           // [M, 3C]
__device__ float g_q[Bv*Hv*Nv*Dv];         // [B,H,N,D] (pre-scaled by 1/sqrt(D))
__device__ float g_k[Bv*Hv*Nv*Dv];
__device__ float g_v[Bv*Hv*Nv*Dv];
__device__ float g_att[Mv * Cv];           // [B,N,C]

// ======================= PTX helpers (plain sm_103-legal) ====================
__device__ __forceinline__ uint32_t smem_u32(const void* p) {
    uint32_t a;
    asm("{ .reg .u64 t; cvta.to.shared.u64 t, %1; cvt.u32.u64 %0, t; }"
        : "=r"(a) : "l"(p));
    return a;
}
__device__ __forceinline__ uint32_t tf32r(float f) {
    uint32_t r;
    asm("cvt.rna.tf32.f32 %0, %1;" : "=r"(r) : "f"(f));
    return r;
}
__device__ __forceinline__ void st_tf32x4(float* p, float4 v) {
    uint4 t;
    t.x = tf32r(v.x); t.y = tf32r(v.y); t.z = tf32r(v.z); t.w = tf32r(v.w);
    *(uint4*)p = t;
}

#define LDSM4(r0, r1, r2, r3, addr) \
    asm volatile("ldmatrix.sync.aligned.m8n8.x4.shared.b16 {%0,%1,%2,%3}, [%4];" \
        : "=r"(r0), "=r"(r1), "=r"(r2), "=r"(r3) : "r"(addr))

#define MMA_TF32(c, a, b) \
    asm volatile("mma.sync.aligned.m16n8k8.row.col.f32.tf32.tf32.f32 " \
        "{%0,%1,%2,%3}, {%4,%5,%6,%7}, {%8,%9}, {%0,%1,%2,%3};" \
        : "+f"((c)[0]), "+f"((c)[1]), "+f"((c)[2]), "+f"((c)[3]) \
        : "r"((a)[0]), "r"((a)[1]), "r"((a)[2]), "r"((a)[3]), \
          "r"((b)[0]), "r"((b)[1]))

// ================== mma.sync TF32 NT GEMM: C = A * B^T (+bias) ===============
// A [M,K], Bw [N,K] row-major fp32. Tile 128x128, k-chunk 16, 256 threads.
// Warp grid 2(m) x 4(n): each warp 64x32 = 4 mfrag x 4 nfrag of m16n8k8.
#define GP 20                 // smem pitch in floats (conflict-free for ldmatrix)
#define GTILE (128*GP)

__global__ __launch_bounds__(256) void gemm_mma(
    const float* __restrict__ A, const float* __restrict__ Bw,
    float* __restrict__ C, int Nn, int K, const float* __restrict__ bias)
{
    __shared__ float As[2][GTILE];
    __shared__ float Bs[2][GTILE];
    const int tid = threadIdx.x, l = tid & 31, w = tid >> 5;
    const int wm = (w & 1) * 64, wn = (w >> 1) * 32;
    const int bm = blockIdx.y * 128, bn = blockIdx.x * 128;

    // global load slots: 128 rows x 4 float4 cols, 2 per thread
    const int r0 = tid >> 2, c4 = (tid & 3) * 4;
    const float* Ap0 = A  + (size_t)(bm + r0)      * K + c4;
    const float* Ap1 = A  + (size_t)(bm + r0 + 64) * K + c4;
    const float* Bp0 = Bw + (size_t)(bn + r0)      * K + c4;
    const float* Bp1 = Bw + (size_t)(bn + r0 + 64) * K + c4;

    const uint32_t As_u = smem_u32(As), Bs_u = smem_u32(Bs);

    // per-lane ldmatrix offsets (floats):
    // A (m16k8 frag): row = wm + mi*16 + (l&15), col = ((l>>4)&1)*4 (+k0)
    // B (x4 covers 2 nfrags): row = wn + p*16 + ((l>>4)<<3) + (l&7),
    //                         col = ((l>>3)&1)*4 (+k0)
    int aoff[4], boff[2];
#pragma unroll
    for (int mi = 0; mi < 4; mi++)
        aoff[mi] = (wm + mi * 16 + (l & 15)) * GP + ((l >> 4) & 1) * 4;
#pragma unroll
    for (int p = 0; p < 2; p++)
        boff[p] = (wn + p * 16 + ((l >> 4) << 3) + (l & 7)) * GP + ((l >> 3) & 1) * 4;

    float acc[4][4][4];
#pragma unroll
    for (int mi = 0; mi < 4; mi++)
#pragma unroll
        for (int ni = 0; ni < 4; ni++)
#pragma unroll
            for (int e = 0; e < 4; e++) acc[mi][ni][e] = 0.f;

    float4 ar0 = *(const float4*)Ap0, ar1 = *(const float4*)Ap1;
    float4 br0 = *(const float4*)Bp0, br1 = *(const float4*)Bp1;

    const int NIT = K / 16;
    for (int i = 0; i < NIT; i++) {
        const int s = i & 1;
        float* as = As[s];
        float* bs = Bs[s];
        st_tf32x4(as + r0 * GP + c4, ar0);
        st_tf32x4(as + (r0 + 64) * GP + c4, ar1);
        st_tf32x4(bs + r0 * GP + c4, br0);
        st_tf32x4(bs + (r0 + 64) * GP + c4, br1);
        __syncthreads();
        if (i + 1 < NIT) {
            const int k0 = (i + 1) * 16;
            ar0 = *(const float4*)(Ap0 + k0); ar1 = *(const float4*)(Ap1 + k0);
            br0 = *(const float4*)(Bp0 + k0); br1 = *(const float4*)(Bp1 + k0);
        }
        const uint32_t au = As_u + s * (GTILE * 4);
        const uint32_t bu = Bs_u + s * (GTILE * 4);
#pragma unroll
        for (int ks = 0; ks < 2; ks++) {
            const int k0 = ks * 8;
            uint32_t a[4][4], b[4][2];
#pragma unroll
            for (int mi = 0; mi < 4; mi++)
                LDSM4(a[mi][0], a[mi][1], a[mi][2], a[mi][3],
                      au + (uint32_t)(aoff[mi] + k0) * 4);
#pragma unroll
            for (int p = 0; p < 2; p++)
                LDSM4(b[2*p][0], b[2*p][1], b[2*p+1][0], b[2*p+1][1],
                      bu + (uint32_t)(boff[p] + k0) * 4);
#pragma unroll
            for (int mi = 0; mi < 4; mi++)
#pragma unroll
                for (int ni = 0; ni < 4; ni++)
                    MMA_TF32(acc[mi][ni], a[mi], b[ni]);
        }
    }

    // epilogue: accum layout c0:(r,2c) c1:(r,2c+1) c2:(r+8,2c) c3:(r+8,2c+1)
    const int rr = l >> 2, cc = (l & 3) * 2;
#pragma unroll
    for (int mi = 0; mi < 4; mi++) {
#pragma unroll
        for (int ni = 0; ni < 4; ni++) {
            const int row = bm + wm + mi * 16 + rr;
            const int col = bn + wn + ni * 8 + cc;
            float b0 = 0.f, b1 = 0.f;
            if (bias) { b0 = bias[col]; b1 = bias[col + 1]; }
            float2 v0 = make_float2(acc[mi][ni][0] + b0, acc[mi][ni][1] + b1);
            float2 v1 = make_float2(acc[mi][ni][2] + b0, acc[mi][ni][3] + b1);
            *(float2*)(C + (size_t)row * Nn + col) = v0;
            *(float2*)(C + (size_t)(row + 8) * Nn + col) = v1;
        }
    }
}

// ---------------- RoPE + transpose to [B,H,N,D] ------------------------------
__global__ __launch_bounds__(256) void rope_transpose(
    const float* __restrict__ qkv, float* __restrict__ q, float* __restrict__ k,
    float* __restrict__ v, const float* __restrict__ ct, const float* __restrict__ st)
{
    int idx = blockIdx.x * 256 + threadIdx.x;       // [0, B*H*N*32)
    int dh = idx & 31;
    int n  = (idx >> 5) & (Nv - 1);
    int h  = (idx >> 16) & (Hv - 1);
    int b  = idx >> 20;

    size_t base = (size_t)(b * Nv + n) * F3 + h * 64;
    float xq0 = qkv[base + dh],        xq1 = qkv[base + dh + 32];
    float xk0 = qkv[base + Cv + dh],   xk1 = qkv[base + Cv + dh + 32];
    float xv0 = qkv[base + 2*Cv + dh], xv1 = qkv[base + 2*Cv + dh + 32];

    float c0 = ct[n * 64 + dh], c1 = ct[n * 64 + dh + 32];
    float s0 = st[n * 64 + dh], s1 = st[n * 64 + dh + 32];

    const float scale = 0.125f;  // D^-0.5, folded into q
    float q0 = (xq0 * c0 - xq1 * s0) * scale;
    float q1 = (xq1 * c1 + xq0 * s1) * scale;
    float k0 = xk0 * c0 - xk1 * s0;
    float k1 = xk1 * c1 + xk0 * s1;

    size_t obase = (size_t)(idx >> 5) * 64 + dh;    // ((b*H+h)*N+n)*64 + dh
    q[obase] = q0;  q[obase + 32] = q1;
    k[obase] = k0;  k[obase + 32] = k1;
    v[obase] = xv0; v[obase + 32] = xv1;
}

// ---------------- Flash attention with mma.sync TF32 -------------------------
// Block: 128 threads (4 warps), 64 q-rows (16 per warp), Bc=64, D=64.
// Warp owns whole rows -> softmax row reductions are quad shuffles.
#define AP 68                          // smem pitch (floats), conflict-free
#define ATT_SMEM (4 * 64 * AP * 4)

__global__ __launch_bounds__(128) void attn_mma(
    const float* __restrict__ q, const float* __restrict__ k,
    const float* __restrict__ v, float* __restrict__ out)
{
    extern __shared__ float sm[];
    float* Qs = sm;                 // [m][d]   64 x AP
    float* Ks = Qs + 64 * AP;       // [kv][d]
    float* Vs = Ks + 64 * AP;       // [d][kv]  (transposed)
    float* Ps = Vs + 64 * AP;       // [m][kv]  (warp-private rows)

    const int bh = blockIdx.y, qt = blockIdx.x;
    const float* qb = q + (size_t)bh * Nv * Dv;
    const float* kb = k + (size_t)bh * Nv * Dv;
    const float* vb = v + (size_t)bh * Nv * Dv;
    const int tid = threadIdx.x, l = tid & 31, w = tid >> 5;
    const int wbase = w * 16;

    const uint32_t Qu = smem_u32(Qs), Ku = smem_u32(Ks);
    const uint32_t Vu = smem_u32(Vs), Pu = smem_u32(Ps);

    // load Q tile (tf32)
    const float* qp = qb + (size_t)qt * 64 * 64;
#pragma unroll
    for (int j = 0; j < 8; j++) {
        int idx = tid + 128 * j;
        int r = idx >> 4, c = (idx & 15) * 4;
        st_tf32x4(Qs + r * AP + c, *(const float4*)(qp + r * 64 + c));
    }

    // lane ldmatrix offsets (floats)
    const int qoff = (wbase + (l & 15)) * AP + ((l >> 4) & 1) * 4;   // A: Qs/Ps
    int koff[4];                                                     // B: Ks/Vs
#pragma unroll
    for (int p = 0; p < 4; p++)
        koff[p] = (p * 16 + ((l >> 4) << 3) + (l & 7)) * AP + ((l >> 3) & 1) * 4;

    float o[8][4];
#pragma unroll
    for (int ni = 0; ni < 8; ni++)
#pragma unroll
        for (int e = 0; e < 4; e++) o[ni][e] = 0.f;
    float m0 = -1e30f, m1 = -1e30f, l0 = 0.f, l1 = 0.f;
    __syncthreads();

    for (int kt = 0; kt < Nv / 64; kt++) {
        const float* kp = kb + (size_t)kt * 64 * 64;
        const float* vp = vb + (size_t)kt * 64 * 64;
#pragma unroll
        for (int j = 0; j < 8; j++) {
            int idx = tid + 128 * j;
            int r = idx >> 4, c = (idx & 15) * 4;
            st_tf32x4(Ks + r * AP + c, *(const float4*)(kp + r * 64 + c));
            float4 u = *(const float4*)(vp + r * 64 + c);
            Vs[(c + 0) * AP + r] = __uint_as_float(tf32r(u.x));
            Vs[(c + 1) * AP + r] = __uint_as_float(tf32r(u.y));
            Vs[(c + 2) * AP + r] = __uint_as_float(tf32r(u.z));
            Vs[(c + 3) * AP + r] = __uint_as_float(tf32r(u.w));
        }
        __syncthreads();

        // S = Q K^T : per warp 16x64, 8 nfrags
        float s[8][4];
#pragma unroll
        for (int ni = 0; ni < 8; ni++)
#pragma unroll
            for (int e = 0; e < 4; e++) s[ni][e] = 0.f;
#pragma unroll
        for (int ks = 0; ks < 8; ks++) {
            const int k0 = ks * 8;
            uint32_t a[4], b[8][2];
            LDSM4(a[0], a[1], a[2], a[3], Qu + (uint32_t)(qoff + k0) * 4);
#pragma unroll
            for (int p = 0; p < 4; p++)
                LDSM4(b[2*p][0], b[2*p][1], b[2*p+1][0], b[2*p+1][1],
                      Ku + (uint32_t)(koff[p] + k0) * 4);
#pragma unroll
            for (int ni = 0; ni < 8; ni++) MMA_TF32(s[ni], a, b[ni]);
        }

        // online softmax: rows r = l>>2 (regs 0,1) and r+8 (regs 2,3)
        float mx0 = -1e30f, mx1 = -1e30f;
#pragma unroll
        for (int ni = 0; ni < 8; ni++) {
            mx0 = fmaxf(mx0, fmaxf(s[ni][0], s[ni][1]));
            mx1 = fmaxf(mx1, fmaxf(s[ni][2], s[ni][3]));
        }
        mx0 = fmaxf(mx0, __shfl_xor_sync(0xffffffffu, mx0, 1));
        mx0 = fmaxf(mx0, __shfl_xor_sync(0xffffffffu, mx0, 2));
        mx1 = fmaxf(mx1, __shfl_xor_sync(0xffffffffu, mx1, 1));
        mx1 = fmaxf(mx1, __shfl_xor_sync(0xffffffffu, mx1, 2));

        const float nm0 = fmaxf(m0, mx0), nm1 = fmaxf(m1, mx1);
        const float al0 = __expf(m0 - nm0), al1 = __expf(m1 - nm1);
        float rs0 = 0.f, rs1 = 0.f;
#pragma unroll
        for (int ni = 0; ni < 8; ni++) {
            s[ni][0] = __expf(s[ni][0] - nm0); rs0 += s[ni][0];
            s[ni][1] = __expf(s[ni][1] - nm0); rs0 += s[ni][1];
            s[ni][2] = __expf(s[ni][2] - nm1); rs1 += s[ni][2];
            s[ni][3] = __expf(s[ni][3] - nm1); rs1 += s[ni][3];
        }
        rs0 += __shfl_xor_sync(0xffffffffu, rs0, 1);
        rs0 += __shfl_xor_sync(0xffffffffu, rs0, 2);
        rs1 += __shfl_xor_sync(0xffffffffu, rs1, 1);
        rs1 += __shfl_xor_sync(0xffffffffu, rs1, 2);
        l0 = l0 * al0 + rs0; m0 = nm0;
        l1 = l1 * al1 + rs1; m1 = nm1;
#pragma unroll
        for (int ni = 0; ni < 8; ni++) {
            o[ni][0] *= al0; o[ni][1] *= al0;
            o[ni][2] *= al1; o[ni][3] *= al1;
        }

        // store P (tf32) into warp-private rows of Ps
        const int pr = wbase + (l >> 2), pc = (l & 3) * 2;
#pragma unroll
        for (int ni = 0; ni < 8; ni++) {
            uint2 p0, p1;
            p0.x = tf32r(s[ni][0]); p0.y = tf32r(s[ni][1]);
            p1.x = tf32r(s[ni][2]); p1.y = tf32r(s[ni][3]);
            *(uint2*)(Ps + pr * AP + ni * 8 + pc) = p0;
            *(uint2*)(Ps + (pr + 8) * AP + ni * 8 + pc) = p1;
        }
        __syncwarp();

        // O += P V : A from Ps, B from Vs[d][kv]
#pragma unroll
        for (int ks = 0; ks < 8; ks++) {
            const int k0 = ks * 8;
            uint32_t a[4], b[8][2];
            LDSM4(a[0], a[1], a[2], a[3], Pu + (uint32_t)(qoff + k0) * 4);
#pragma unroll
            for (int p = 0; p < 4; p++)
                LDSM4(b[2*p][0], b[2*p][1], b[2*p+1][0], b[2*p+1][1],
                      Vu + (uint32_t)(koff[p] + k0) * 4);
#pragma unroll
            for (int ni = 0; ni < 8; ni++) MMA_TF32(o[ni], a, b[ni]);
        }
        __syncthreads();
    }

    // epilogue -> att [B,N,C]
    const int b_ = bh >> 4, h_ = bh & 15;
    const float i0 = 1.f / l0, i1 = 1.f / l1;
    const int n0 = qt * 64 + wbase + (l >> 2);
#pragma unroll
    for (int ni = 0; ni < 8; ni++) {
        const int col = h_ * 64 + ni * 8 + (l & 3) * 2;
        float2 v0 = make_float2(o[ni][0] * i0, o[ni][1] * i0);
        float2 v1 = make_float2(o[ni][2] * i1, o[ni][3] * i1);
        *(float2*)(out + (size_t)(b_ * Nv + n0) * Cv + col) = v0;
        *(float2*)(out + (size_t)(b_ * Nv + n0 + 8) * Cv + col) = v1;
    }
}

// ---------------- launch -----------------------------------------------------
extern "C" void kernel_launch(void* const* d_in, const int* in_sizes, int n_in,
                              void* d_out, int out_size)
{
    const float* x        = (const float*)d_in[0];
    const float* rope_cos = (const float*)d_in[1];
    const float* rope_sin = (const float*)d_in[2];
    const float* w_qkv    = (const float*)d_in[3];
    const float* w_proj   = (const float*)d_in[4];
    const float* b_proj   = (const float*)d_in[5];
    float* out = (float*)d_out;

    float *qkv, *q, *k, *v, *att;
    cudaGetSymbolAddress((void**)&qkv, g_qkv);
    cudaGetSymbolAddress((void**)&q,   g_q);
    cudaGetSymbolAddress((void**)&k,   g_k);
    cudaGetSymbolAddress((void**)&v,   g_v);
    cudaGetSymbolAddress((void**)&att, g_att);

    cudaFuncSetAttribute(attn_mma, cudaFuncAttributeMaxDynamicSharedMemorySize, ATT_SMEM);

    // 1) QKV GEMM: [8192,1024] x [3072,1024]^T -> [8192,3072]
    gemm_mma<<<dim3(F3 / 128, Mv / 128), 256>>>(x, w_qkv, qkv, F3, Cv, nullptr);

    // 2) RoPE + transpose to [B,H,N,D]
    rope_transpose<<<(Bv * Hv * Nv * 32) / 256, 256>>>(qkv, q, k, v, rope_cos, rope_sin);

    // 3) Flash attention (tensor cores)
    attn_mma<<<dim3(Nv / 64, Bv * Hv), 128, ATT_SMEM>>>(q, k, v, att);

    // 4) projection + bias: [8192,1024] x [1024,1024]^T -> d_out
    gemm_mma<<<dim3(Cv / 128, Mv / 128), 256>>>(att, w_proj, out, Cv, Cv, b_proj);
}

// round 5
// speedup vs baseline: 4.1157x; 1.3414x over previous
#include <cuda_runtime.h>
#include <math.h>
#include <stdint.h>

#define Bv 4
#define Nv 2048
#define Cv 1024
#define Hv 16
#define Dv 64
#define Mv (Bv*Nv)          // 8192
#define F3 (3*Cv)           // 3072

// ---------------- scratch (static device arrays; no allocation) --------------
__device__ float g_qkv[Mv * F3];           // [M, 3C] fp32 accum
__device__ float g_q[Bv*Hv*Nv*Dv];         // [B,H,N,D] tf32-rounded, pre-scaled
__device__ float g_k[Bv*Hv*Nv*Dv];         // [B,H,N,D] tf32-rounded
__device__ float g_vT[Bv*Hv*Dv*Nv];        // [B,H,D,N] tf32-rounded (transposed!)
__device__ float g_att[Mv * Cv];           // [B,N,C] tf32-rounded
__device__ float g_xr[Mv * Cv];            // x rounded
__device__ float g_wqkvr[F3 * Cv];         // w_qkv rounded
__device__ float g_wprojr[Cv * Cv];        // w_proj rounded

// ======================= PTX helpers (plain sm_103-legal) ====================
__device__ __forceinline__ uint32_t smem_u32(const void* p) {
    uint32_t a;
    asm("{ .reg .u64 t; cvta.to.shared.u64 t, %1; cvt.u32.u64 %0, t; }"
        : "=r"(a) : "l"(p));
    return a;
}
__device__ __forceinline__ uint32_t tf32r(float f) {
    uint32_t r;
    asm("cvt.rna.tf32.f32 %0, %1;" : "=r"(r) : "f"(f));
    return r;
}
__device__ __forceinline__ void cpa16(uint32_t dst, const void* src) {
    asm volatile("cp.async.cg.shared.global [%0], [%1], 16;"
                 :: "r"(dst), "l"(src));
}
#define CP_COMMIT() asm volatile("cp.async.commit_group;" ::: "memory")
#define CP_WAIT(n)  asm volatile("cp.async.wait_group %0;" :: "n"(n) : "memory")

#define LDSM4(r0, r1, r2, r3, addr) \
    asm volatile("ldmatrix.sync.aligned.m8n8.x4.shared.b16 {%0,%1,%2,%3}, [%4];" \
        : "=r"(r0), "=r"(r1), "=r"(r2), "=r"(r3) : "r"(addr))

#define MMA_TF32(c, a, b) \
    asm volatile("mma.sync.aligned.m16n8k8.row.col.f32.tf32.tf32.f32 " \
        "{%0,%1,%2,%3}, {%4,%5,%6,%7}, {%8,%9}, {%0,%1,%2,%3};" \
        : "+f"((c)[0]), "+f"((c)[1]), "+f"((c)[2]), "+f"((c)[3]) \
        : "r"((a)[0]), "r"((a)[1]), "r"((a)[2]), "r"((a)[3]), \
          "r"((b)[0]), "r"((b)[1]))

// ---------------- elementwise tf32 rounding ----------------------------------
__global__ __launch_bounds__(256) void round_tf32(const float4* __restrict__ in,
                                                  float4* __restrict__ out, int n4)
{
    int i = blockIdx.x * 256 + threadIdx.x;
    if (i < n4) {
        float4 v = in[i];
        uint4 t;
        t.x = tf32r(v.x); t.y = tf32r(v.y); t.z = tf32r(v.z); t.w = tf32r(v.w);
        *(uint4*)&out[i] = t;
    }
}

// ================== cp.async 4-stage TF32 GEMM: C = A * B^T (+bias) ==========
// A [M,K], Bw [N,K] tf32-rounded fp32. Tile 128x128, k-chunk 16, 256 threads.
#define GP 20
#define GSTAGE (128*GP)                    // floats per operand per stage
#define GEMM_SMEM (4 * 2 * GSTAGE * 4)     // 81920 B

__global__ __launch_bounds__(256, 2) void gemm_mma(
    const float* __restrict__ A, const float* __restrict__ Bw,
    float* __restrict__ C, int Nn, int K, const float* __restrict__ bias)
{
    extern __shared__ float sm[];
    const int tid = threadIdx.x, l = tid & 31, w = tid >> 5;
    const int wm = (w & 1) * 64, wn = (w >> 1) * 32;
    const int bm = blockIdx.y * 128, bn = blockIdx.x * 128;
    const uint32_t base_u = smem_u32(sm);

    const float* Ag = A  + (size_t)bm * K;
    const float* Bg = Bw + (size_t)bn * K;

    // per-lane ldmatrix offsets (floats)
    int aoff[4], boff[2];
#pragma unroll
    for (int mi = 0; mi < 4; mi++)
        aoff[mi] = (wm + mi * 16 + (l & 15)) * GP + ((l >> 4) & 1) * 4;
#pragma unroll
    for (int p = 0; p < 2; p++)
        boff[p] = (wn + p * 16 + ((l >> 4) << 3) + (l & 7)) * GP + ((l >> 3) & 1) * 4;

    // cp.async chunk mapping: 2 chunks per thread per operand
    const int crow0 = tid >> 2, cks0 = (tid & 3) * 4;
    const int crow1 = (tid + 256) >> 2, cks1 = cks0;

    float acc[4][4][4];
#pragma unroll
    for (int mi = 0; mi < 4; mi++)
#pragma unroll
        for (int ni = 0; ni < 4; ni++)
#pragma unroll
            for (int e = 0; e < 4; e++) acc[mi][ni][e] = 0.f;

    const int NIT = K / 16;

    auto issue = [&](int i) {
        const int k0 = i * 16;
        const int st = i & 3;
        const uint32_t au = base_u + (uint32_t)(st * 2 * GSTAGE) * 4;
        const uint32_t bu = au + GSTAGE * 4;
        cpa16(au + (uint32_t)(crow0 * GP + cks0) * 4, Ag + (size_t)crow0 * K + k0 + cks0);
        cpa16(au + (uint32_t)(crow1 * GP + cks1) * 4, Ag + (size_t)crow1 * K + k0 + cks1);
        cpa16(bu + (uint32_t)(crow0 * GP + cks0) * 4, Bg + (size_t)crow0 * K + k0 + cks0);
        cpa16(bu + (uint32_t)(crow1 * GP + cks1) * 4, Bg + (size_t)crow1 * K + k0 + cks1);
    };

    issue(0); CP_COMMIT();
    issue(1); CP_COMMIT();
    issue(2); CP_COMMIT();

    for (int i = 0; i < NIT; i++) {
        if (i < NIT - 2)      { CP_WAIT(2); }
        else if (i == NIT - 2){ CP_WAIT(1); }
        else                  { CP_WAIT(0); }
        __syncthreads();
        if (i + 3 < NIT) { issue(i + 3); CP_COMMIT(); }

        const int st = i & 3;
        const uint32_t au = base_u + (uint32_t)(st * 2 * GSTAGE) * 4;
        const uint32_t bu = au + GSTAGE * 4;
#pragma unroll
        for (int ks = 0; ks < 2; ks++) {
            const int k0 = ks * 8;
            uint32_t a[4][4], b[4][2];
#pragma unroll
            for (int mi = 0; mi < 4; mi++)
                LDSM4(a[mi][0], a[mi][1], a[mi][2], a[mi][3],
                      au + (uint32_t)(aoff[mi] + k0) * 4);
#pragma unroll
            for (int p = 0; p < 2; p++)
                LDSM4(b[2*p][0], b[2*p][1], b[2*p+1][0], b[2*p+1][1],
                      bu + (uint32_t)(boff[p] + k0) * 4);
#pragma unroll
            for (int mi = 0; mi < 4; mi++)
#pragma unroll
                for (int ni = 0; ni < 4; ni++)
                    MMA_TF32(acc[mi][ni], a[mi], b[ni]);
        }
        __syncthreads();
    }

    const int rr = l >> 2, cc = (l & 3) * 2;
#pragma unroll
    for (int mi = 0; mi < 4; mi++) {
#pragma unroll
        for (int ni = 0; ni < 4; ni++) {
            const int row = bm + wm + mi * 16 + rr;
            const int col = bn + wn + ni * 8 + cc;
            float b0 = 0.f, b1 = 0.f;
            if (bias) { b0 = bias[col]; b1 = bias[col + 1]; }
            float2 v0 = make_float2(acc[mi][ni][0] + b0, acc[mi][ni][1] + b1);
            float2 v1 = make_float2(acc[mi][ni][2] + b0, acc[mi][ni][3] + b1);
            *(float2*)(C + (size_t)row * Nn + col) = v0;
            *(float2*)(C + (size_t)(row + 8) * Nn + col) = v1;
        }
    }
}

// ---------------- RoPE + transpose; writes tf32-rounded q,k and vT -----------
__global__ __launch_bounds__(256) void rope_transpose(
    const float* __restrict__ qkv, float* __restrict__ q, float* __restrict__ k,
    float* __restrict__ vT, const float* __restrict__ ct, const float* __restrict__ st)
{
    __shared__ float sv[64][9];
    int idx = blockIdx.x * 256 + threadIdx.x;       // [0, B*H*N*32)
    int tid = threadIdx.x;
    int dh = idx & 31;
    int n  = (idx >> 5) & (Nv - 1);
    int bh = idx >> 16;                              // b*H + h

    size_t base = (size_t)(((bh >> 4) * Nv) + n) * F3 + (bh & (Hv - 1)) * 64;

    float xq0 = qkv[base + dh],        xq1 = qkv[base + dh + 32];
    float xk0 = qkv[base + Cv + dh],   xk1 = qkv[base + Cv + dh + 32];
    float xv0 = qkv[base + 2*Cv + dh], xv1 = qkv[base + 2*Cv + dh + 32];

    float c0 = ct[n * 64 + dh], c1 = ct[n * 64 + dh + 32];
    float s0 = st[n * 64 + dh], s1 = st[n * 64 + dh + 32];

    const float scale = 0.125f;  // D^-0.5, folded into q
    float q0 = (xq0 * c0 - xq1 * s0) * scale;
    float q1 = (xq1 * c1 + xq0 * s1) * scale;
    float k0 = xk0 * c0 - xk1 * s0;
    float k1 = xk1 * c1 + xk0 * s1;

    size_t obase = (size_t)(idx >> 5) * 64 + dh;    // ((b*H+h)*N+n)*64 + dh
    q[obase] = __uint_as_float(tf32r(q0));  q[obase + 32] = __uint_as_float(tf32r(q1));
    k[obase] = __uint_as_float(tf32r(k0));  k[obase + 32] = __uint_as_float(tf32r(k1));

    // stage v into smem, write transposed [bh][d][n]
    int np = (tid >> 5) & 7;
    sv[dh][np]      = __uint_as_float(tf32r(xv0));
    sv[dh + 32][np] = __uint_as_float(tf32r(xv1));
    __syncthreads();
    int n0 = n & ~7;
#pragma unroll
    for (int j = 0; j < 2; j++) {
        int e = tid + 256 * j;
        int d = e >> 3, nn = e & 7;
        vT[((size_t)bh * 64 + d) * Nv + n0 + nn] = sv[d][nn];
    }
}

// ---------------- Flash attention, mma.sync TF32, cp.async pipelined ---------
// Br=128 (8 warps x 16 rows), Bc=64, D=64. Q frags hoisted to regs; Q smem
// region reused for P. K/V double-buffered.
#define AP 68
#define ATT_SMEM (384 * AP * 4)        // Qs/Ps 128 + Ks 2x64 + Vs 2x64 rows

__global__ __launch_bounds__(256, 2) void attn_mma(
    const float* __restrict__ q, const float* __restrict__ k,
    const float* __restrict__ vT, float* __restrict__ out)
{
    extern __shared__ float sm[];
    const int bh = blockIdx.y, qt = blockIdx.x;
    const float* qb  = q  + (size_t)bh * Nv * Dv;
    const float* kb  = k  + (size_t)bh * Nv * Dv;
    const float* vTb = vT + (size_t)bh * Dv * Nv;
    const int tid = threadIdx.x, l = tid & 31, w = tid >> 5;
    const int wbase = w * 16;

    const uint32_t Qu = smem_u32(sm);
    uint32_t Ku[2], Vu[2];
    Ku[0] = Qu + 128 * AP * 4;  Ku[1] = Qu + 192 * AP * 4;
    Vu[0] = Qu + 256 * AP * 4;  Vu[1] = Qu + 320 * AP * 4;

    // lane ldmatrix offsets (floats)
    const int qoff = (wbase + (l & 15)) * AP + ((l >> 4) & 1) * 4;
    int koff[4];
#pragma unroll
    for (int p = 0; p < 4; p++)
        koff[p] = (p * 16 + ((l >> 4) << 3) + (l & 7)) * AP + ((l >> 3) & 1) * 4;

    // K/V tile load: 64 rows x 64 cols = 1024 chunks -> 4 per thread per operand
    auto issue_kv = [&](int kt) {
        const int slot = kt & 1;
#pragma unroll
        for (int j = 0; j < 4; j++) {
            int c = tid + 256 * j;
            int row = c >> 4, ks = (c & 15) * 4;
            cpa16(Ku[slot] + (uint32_t)(row * AP + ks) * 4,
                  kb + (size_t)(kt * 64 + row) * 64 + ks);
            cpa16(Vu[slot] + (uint32_t)(row * AP + ks) * 4,
                  vTb + (size_t)row * Nv + kt * 64 + ks);
        }
    };

    // prologue: Q tile 128x64 = 2048 chunks -> 8 per thread
    {
        const float* qp = qb + (size_t)qt * 128 * 64;
#pragma unroll
        for (int j = 0; j < 8; j++) {
            int c = tid + 256 * j;
            int row = c >> 4, ks = (c & 15) * 4;
            cpa16(Qu + (uint32_t)(row * AP + ks) * 4, qp + (size_t)row * 64 + ks);
        }
        CP_COMMIT();
        issue_kv(0); CP_COMMIT();
    }

    float o[8][4];
#pragma unroll
    for (int ni = 0; ni < 8; ni++)
#pragma unroll
        for (int e = 0; e < 4; e++) o[ni][e] = 0.f;
    float m0 = -1e30f, m1 = -1e30f, l0 = 0.f, l1 = 0.f;

    // hoist Q fragments (warp-private rows -> no cross-warp hazard with P reuse)
    uint32_t qa[8][4];
    CP_WAIT(1);                 // Q arrived (KV0 may still be in flight)
    __syncthreads();
#pragma unroll
    for (int ks = 0; ks < 8; ks++)
        LDSM4(qa[ks][0], qa[ks][1], qa[ks][2], qa[ks][3],
              Qu + (uint32_t)(qoff + ks * 8) * 4);
    __syncwarp();

    const int NT = Nv / 64;     // 32
    for (int kt = 0; kt < NT; kt++) {
        if (kt + 1 < NT) { issue_kv(kt + 1); CP_COMMIT(); CP_WAIT(1); }
        else             { CP_WAIT(0); }
        __syncthreads();

        const int slot = kt & 1;
        // S = Q K^T : per warp 16x64
        float s[8][4];
#pragma unroll
        for (int ni = 0; ni < 8; ni++)
#pragma unroll
            for (int e = 0; e < 4; e++) s[ni][e] = 0.f;
#pragma unroll
        for (int ks = 0; ks < 8; ks++) {
            const int k0 = ks * 8;
            uint32_t b[8][2];
#pragma unroll
            for (int p = 0; p < 4; p++)
                LDSM4(b[2*p][0], b[2*p][1], b[2*p+1][0], b[2*p+1][1],
                      Ku[slot] + (uint32_t)(koff[p] + k0) * 4);
#pragma unroll
            for (int ni = 0; ni < 8; ni++) MMA_TF32(s[ni], qa[ks], b[ni]);
        }

        // online softmax (rows l>>2, l>>2 + 8)
        float mx0 = -1e30f, mx1 = -1e30f;
#pragma unroll
        for (int ni = 0; ni < 8; ni++) {
            mx0 = fmaxf(mx0, fmaxf(s[ni][0], s[ni][1]));
            mx1 = fmaxf(mx1, fmaxf(s[ni][2], s[ni][3]));
        }
        mx0 = fmaxf(mx0, __shfl_xor_sync(0xffffffffu, mx0, 1));
        mx0 = fmaxf(mx0, __shfl_xor_sync(0xffffffffu, mx0, 2));
        mx1 = fmaxf(mx1, __shfl_xor_sync(0xffffffffu, mx1, 1));
        mx1 = fmaxf(mx1, __shfl_xor_sync(0xffffffffu, mx1, 2));

        const float nm0 = fmaxf(m0, mx0), nm1 = fmaxf(m1, mx1);
        const float al0 = __expf(m0 - nm0), al1 = __expf(m1 - nm1);
        float rs0 = 0.f, rs1 = 0.f;
#pragma unroll
        for (int ni = 0; ni < 8; ni++) {
            s[ni][0] = __expf(s[ni][0] - nm0); rs0 += s[ni][0];
            s[ni][1] = __expf(s[ni][1] - nm0); rs0 += s[ni][1];
            s[ni][2] = __expf(s[ni][2] - nm1); rs1 += s[ni][2];
            s[ni][3] = __expf(s[ni][3] - nm1); rs1 += s[ni][3];
        }
        rs0 += __shfl_xor_sync(0xffffffffu, rs0, 1);
        rs0 += __shfl_xor_sync(0xffffffffu, rs0, 2);
        rs1 += __shfl_xor_sync(0xffffffffu, rs1, 1);
        rs1 += __shfl_xor_sync(0xffffffffu, rs1, 2);
        l0 = l0 * al0 + rs0; m0 = nm0;
        l1 = l1 * al1 + rs1; m1 = nm1;
#pragma unroll
        for (int ni = 0; ni < 8; ni++) {
            o[ni][0] *= al0; o[ni][1] *= al0;
            o[ni][2] *= al1; o[ni][3] *= al1;
        }

        // P (tf32) -> warp-private rows of the Q/P region
        const int pr = wbase + (l >> 2), pc = (l & 3) * 2;
        float* Ps = sm;
        __syncwarp();
#pragma unroll
        for (int ni = 0; ni < 8; ni++) {
            uint2 p0, p1;
            p0.x = tf32r(s[ni][0]); p0.y = tf32r(s[ni][1]);
            p1.x = tf32r(s[ni][2]); p1.y = tf32r(s[ni][3]);
            *(uint2*)(Ps + pr * AP + ni * 8 + pc) = p0;
            *(uint2*)(Ps + (pr + 8) * AP + ni * 8 + pc) = p1;
        }
        __syncwarp();

        // O += P V
#pragma unroll
        for (int ks = 0; ks < 8; ks++) {
            const int k0 = ks * 8;
            uint32_t a[4], b[8][2];
            LDSM4(a[0], a[1], a[2], a[3], Qu + (uint32_t)(qoff + k0) * 4);
#pragma unroll
            for (int p = 0; p < 4; p++)
                LDSM4(b[2*p][0], b[2*p][1], b[2*p+1][0], b[2*p+1][1],
                      Vu[slot] + (uint32_t)(koff[p] + k0) * 4);
#pragma unroll
            for (int ni = 0; ni < 8; ni++) MMA_TF32(o[ni], a, b[ni]);
        }
        __syncthreads();
    }

    // epilogue -> att [B,N,C], tf32-rounded (it feeds the proj GEMM raw)
    const int b_ = bh >> 4, h_ = bh & 15;
    const float i0 = 1.f / l0, i1 = 1.f / l1;
    const int n0 = qt * 128 + wbase + (l >> 2);
#pragma unroll
    for (int ni = 0; ni < 8; ni++) {
        const int col = h_ * 64 + ni * 8 + (l & 3) * 2;
        uint2 v0, v1;
        v0.x = tf32r(o[ni][0] * i0); v0.y = tf32r(o[ni][1] * i0);
        v1.x = tf32r(o[ni][2] * i1); v1.y = tf32r(o[ni][3] * i1);
        *(uint2*)(out + (size_t)(b_ * Nv + n0) * Cv + col) = v0;
        *(uint2*)(out + (size_t)(b_ * Nv + n0 + 8) * Cv + col) = v1;
    }
}

// ---------------- launch -----------------------------------------------------
extern "C" void kernel_launch(void* const* d_in, const int* in_sizes, int n_in,
                              void* d_out, int out_size)
{
    const float* x        = (const float*)d_in[0];
    const float* rope_cos = (const float*)d_in[1];
    const float* rope_sin = (const float*)d_in[2];
    const float* w_qkv    = (const float*)d_in[3];
    const float* w_proj   = (const float*)d_in[4];
    const float* b_proj   = (const float*)d_in[5];
    float* out = (float*)d_out;

    float *qkv, *q, *k, *vT, *att, *xr, *wqr, *wpr;
    cudaGetSymbolAddress((void**)&qkv, g_qkv);
    cudaGetSymbolAddress((void**)&q,   g_q);
    cudaGetSymbolAddress((void**)&k,   g_k);
    cudaGetSymbolAddress((void**)&vT,  g_vT);
    cudaGetSymbolAddress((void**)&att, g_att);
    cudaGetSymbolAddress((void**)&xr,  g_xr);
    cudaGetSymbolAddress((void**)&wqr, g_wqkvr);
    cudaGetSymbolAddress((void**)&wpr, g_wprojr);

    cudaFuncSetAttribute(gemm_mma, cudaFuncAttributeMaxDynamicSharedMemorySize, GEMM_SMEM);
    cudaFuncSetAttribute(attn_mma, cudaFuncAttributeMaxDynamicSharedMemorySize, ATT_SMEM);

    // 0) pre-round inputs to tf32-exact fp32 (lets all hot loops cp.async raw)
    round_tf32<<<(Mv * Cv / 4 + 255) / 256, 256>>>((const float4*)x, (float4*)xr, Mv * Cv / 4);
    round_tf32<<<(F3 * Cv / 4 + 255) / 256, 256>>>((const float4*)w_qkv, (float4*)wqr, F3 * Cv / 4);
    round_tf32<<<(Cv * Cv / 4 + 255) / 256, 256>>>((const float4*)w_proj, (float4*)wpr, Cv * Cv / 4);

    // 1) QKV GEMM: [8192,1024] x [3072,1024]^T -> [8192,3072]
    gemm_mma<<<dim3(F3 / 128, Mv / 128), 256, GEMM_SMEM>>>(xr, wqr, qkv, F3, Cv, nullptr);

    // 2) RoPE + transpose (q,k rounded; v rounded + transposed)
    rope_transpose<<<(Bv * Hv * Nv * 32) / 256, 256>>>(qkv, q, k, vT, rope_cos, rope_sin);

    // 3) Flash attention (tensor cores, Br=128, pipelined)
    attn_mma<<<dim3(Nv / 128, Bv * Hv), 256, ATT_SMEM>>>(q, k, vT, att);

    // 4) projection + bias: [8192,1024] x [1024,1024]^T -> d_out
    gemm_mma<<<dim3(Cv / 128, Mv / 128), 256, GEMM_SMEM>>>(att, wpr, out, Cv, Cv, b_proj);
}

// round 6
// speedup vs baseline: 4.4942x; 1.0920x over previous
#include <cuda_runtime.h>
#include <math.h>
#include <stdint.h>

#define Bv 4
#define Nv 2048
#define Cv 1024
#define Hv 16
#define Dv 64
#define Mv (Bv*Nv)          // 8192
#define F3 (3*Cv)           // 3072

// ---------------- scratch (static device arrays; no allocation) --------------
__device__ float g_qkv[Mv * F3];           // [M, 3C] fp32 accum
__device__ float g_q[Bv*Hv*Nv*Dv];         // [B,H,N,D] tf32-rounded, pre-scaled
__device__ float g_k[Bv*Hv*Nv*Dv];         // [B,H,N,D] tf32-rounded
__device__ float g_vT[Bv*Hv*Dv*Nv];        // [B,H,D,N] tf32-rounded (transposed!)
__device__ float g_att[Mv * Cv];           // [B,N,C] tf32-rounded
__device__ float g_xr[Mv * Cv];            // x rounded
__device__ float g_wqkvr[F3 * Cv];         // w_qkv rounded
__device__ float g_wprojr[Cv * Cv];        // w_proj rounded

// ======================= PTX helpers (plain sm_103-legal) ====================
__device__ __forceinline__ uint32_t smem_u32(const void* p) {
    uint32_t a;
    asm("{ .reg .u64 t; cvta.to.shared.u64 t, %1; cvt.u32.u64 %0, t; }"
        : "=r"(a) : "l"(p));
    return a;
}
__device__ __forceinline__ uint32_t tf32r(float f) {
    uint32_t r;
    asm("cvt.rna.tf32.f32 %0, %1;" : "=r"(r) : "f"(f));
    return r;
}
__device__ __forceinline__ void cpa16(uint32_t dst, const void* src) {
    asm volatile("cp.async.cg.shared.global [%0], [%1], 16;"
                 :: "r"(dst), "l"(src));
}
#define CP_COMMIT() asm volatile("cp.async.commit_group;" ::: "memory")
#define CP_WAIT(n)  asm volatile("cp.async.wait_group %0;" :: "n"(n) : "memory")

#define LDSM4(r0, r1, r2, r3, addr) \
    asm volatile("ldmatrix.sync.aligned.m8n8.x4.shared.b16 {%0,%1,%2,%3}, [%4];" \
        : "=r"(r0), "=r"(r1), "=r"(r2), "=r"(r3) : "r"(addr))

#define MMA_TF32(c, a, b) \
    asm volatile("mma.sync.aligned.m16n8k8.row.col.f32.tf32.tf32.f32 " \
        "{%0,%1,%2,%3}, {%4,%5,%6,%7}, {%8,%9}, {%0,%1,%2,%3};" \
        : "+f"((c)[0]), "+f"((c)[1]), "+f"((c)[2]), "+f"((c)[3]) \
        : "r"((a)[0]), "r"((a)[1]), "r"((a)[2]), "r"((a)[3]), \
          "r"((b)[0]), "r"((b)[1]))

// ---------------- elementwise tf32 rounding ----------------------------------
__global__ __launch_bounds__(256) void round_tf32(const float4* __restrict__ in,
                                                  float4* __restrict__ out, int n4)
{
    int i = blockIdx.x * 256 + threadIdx.x;
    if (i < n4) {
        float4 v = in[i];
        uint4 t;
        t.x = tf32r(v.x); t.y = tf32r(v.y); t.z = tf32r(v.z); t.w = tf32r(v.w);
        *(uint4*)&out[i] = t;
    }
}

// ================== cp.async 3-stage TF32 GEMM: C = A * B^T (+bias) ==========
// A [M,K], Bw [N,K] tf32-rounded fp32. Tile 128x128, k-chunk 32, 256 threads.
// One __syncthreads per iteration: wait -> sync -> issue(i+2) -> compute(i).
#define GP 36
#define GSTAGE (128*GP)                    // 4608 floats per operand per stage
#define GEMM_SMEM (3 * 2 * GSTAGE * 4)     // 110592 B

__global__ __launch_bounds__(256, 2) void gemm_mma(
    const float* __restrict__ A, const float* __restrict__ Bw,
    float* __restrict__ C, int Nn, int K, const float* __restrict__ bias)
{
    extern __shared__ float sm[];
    const int tid = threadIdx.x, l = tid & 31, w = tid >> 5;
    const int wm = (w & 1) * 64, wn = (w >> 1) * 32;
    const int bm = blockIdx.y * 128, bn = blockIdx.x * 128;
    const uint32_t base_u = smem_u32(sm);

    const float* Ag = A  + (size_t)bm * K;
    const float* Bg = Bw + (size_t)bn * K;

    // per-lane ldmatrix offsets (floats)
    int aoff[4], boff[2];
#pragma unroll
    for (int mi = 0; mi < 4; mi++)
        aoff[mi] = (wm + mi * 16 + (l & 15)) * GP + ((l >> 4) & 1) * 4;
#pragma unroll
    for (int p = 0; p < 2; p++)
        boff[p] = (wn + p * 16 + ((l >> 4) << 3) + (l & 7)) * GP + ((l >> 3) & 1) * 4;

    float acc[4][4][4];
#pragma unroll
    for (int mi = 0; mi < 4; mi++)
#pragma unroll
        for (int ni = 0; ni < 4; ni++)
#pragma unroll
            for (int e = 0; e < 4; e++) acc[mi][ni][e] = 0.f;

    const int NIT = K / 32;

    // 128 rows x 32 cols = 1024 float4 chunks per operand -> 4 per thread
    auto issue = [&](int i) {
        const int k0 = i * 32;
        const int st = i % 3;
        const uint32_t au = base_u + (uint32_t)(st * 2 * GSTAGE) * 4;
        const uint32_t bu = au + GSTAGE * 4;
#pragma unroll
        for (int j = 0; j < 4; j++) {
            int c = tid + 256 * j;
            int row = c >> 3, col = (c & 7) * 4;
            cpa16(au + (uint32_t)(row * GP + col) * 4, Ag + (size_t)row * K + k0 + col);
            cpa16(bu + (uint32_t)(row * GP + col) * 4, Bg + (size_t)row * K + k0 + col);
        }
    };

    issue(0); CP_COMMIT();
    issue(1); CP_COMMIT();

    for (int i = 0; i < NIT; i++) {
        if (i == NIT - 1) { CP_WAIT(0); } else { CP_WAIT(1); }
        __syncthreads();
        if (i + 2 < NIT) { issue(i + 2); CP_COMMIT(); }

        const int st = i % 3;
        const uint32_t au = base_u + (uint32_t)(st * 2 * GSTAGE) * 4;
        const uint32_t bu = au + GSTAGE * 4;
#pragma unroll
        for (int ks = 0; ks < 4; ks++) {
            const int k0 = ks * 8;
            uint32_t a[4][4], b[4][2];
#pragma unroll
            for (int mi = 0; mi < 4; mi++)
                LDSM4(a[mi][0], a[mi][1], a[mi][2], a[mi][3],
                      au + (uint32_t)(aoff[mi] + k0) * 4);
#pragma unroll
            for (int p = 0; p < 2; p++)
                LDSM4(b[2*p][0], b[2*p][1], b[2*p+1][0], b[2*p+1][1],
                      bu + (uint32_t)(boff[p] + k0) * 4);
#pragma unroll
            for (int mi = 0; mi < 4; mi++)
#pragma unroll
                for (int ni = 0; ni < 4; ni++)
                    MMA_TF32(acc[mi][ni], a[mi], b[ni]);
        }
    }

    const int rr = l >> 2, cc = (l & 3) * 2;
#pragma unroll
    for (int mi = 0; mi < 4; mi++) {
#pragma unroll
        for (int ni = 0; ni < 4; ni++) {
            const int row = bm + wm + mi * 16 + rr;
            const int col = bn + wn + ni * 8 + cc;
            float b0 = 0.f, b1 = 0.f;
            if (bias) { b0 = bias[col]; b1 = bias[col + 1]; }
            float2 v0 = make_float2(acc[mi][ni][0] + b0, acc[mi][ni][1] + b1);
            float2 v1 = make_float2(acc[mi][ni][2] + b0, acc[mi][ni][3] + b1);
            *(float2*)(C + (size_t)row * Nn + col) = v0;
            *(float2*)(C + (size_t)(row + 8) * Nn + col) = v1;
        }
    }
}

// ---------------- RoPE + transpose; writes tf32-rounded q,k and vT -----------
// q is pre-scaled by (1/sqrt(D)) * log2(e) so attention softmax can use exp2.
__global__ __launch_bounds__(256) void rope_transpose(
    const float* __restrict__ qkv, float* __restrict__ q, float* __restrict__ k,
    float* __restrict__ vT, const float* __restrict__ ct, const float* __restrict__ st)
{
    __shared__ float sv[64][9];
    int idx = blockIdx.x * 256 + threadIdx.x;       // [0, B*H*N*32)
    int tid = threadIdx.x;
    int dh = idx & 31;
    int n  = (idx >> 5) & (Nv - 1);
    int bh = idx >> 16;                              // b*H + h

    size_t base = (size_t)(((bh >> 4) * Nv) + n) * F3 + (bh & (Hv - 1)) * 64;

    float xq0 = qkv[base + dh],        xq1 = qkv[base + dh + 32];
    float xk0 = qkv[base + Cv + dh],   xk1 = qkv[base + Cv + dh + 32];
    float xv0 = qkv[base + 2*Cv + dh], xv1 = qkv[base + 2*Cv + dh + 32];

    float c0 = ct[n * 64 + dh], c1 = ct[n * 64 + dh + 32];
    float s0 = st[n * 64 + dh], s1 = st[n * 64 + dh + 32];

    const float scale = 0.125f * 1.4426950408889634f;   // D^-0.5 * log2(e)
    float q0 = (xq0 * c0 - xq1 * s0) * scale;
    float q1 = (xq1 * c1 + xq0 * s1) * scale;
    float k0 = xk0 * c0 - xk1 * s0;
    float k1 = xk1 * c1 + xk0 * s1;

    size_t obase = (size_t)(idx >> 5) * 64 + dh;    // ((b*H+h)*N+n)*64 + dh
    q[obase] = __uint_as_float(tf32r(q0));  q[obase + 32] = __uint_as_float(tf32r(q1));
    k[obase] = __uint_as_float(tf32r(k0));  k[obase + 32] = __uint_as_float(tf32r(k1));

    // stage v into smem, write transposed [bh][d][n]
    int np = (tid >> 5) & 7;
    sv[dh][np]      = __uint_as_float(tf32r(xv0));
    sv[dh + 32][np] = __uint_as_float(tf32r(xv1));
    __syncthreads();
    int n0 = n & ~7;
#pragma unroll
    for (int j = 0; j < 2; j++) {
        int e = tid + 256 * j;
        int d = e >> 3, nn = e & 7;
        vT[((size_t)bh * 64 + d) * Nv + n0 + nn] = sv[d][nn];
    }
}

// ---------------- Flash attention, mma.sync TF32, cp.async pipelined ---------
// Br=128 (8 warps x 16 rows), Bc=64, D=64. One __syncthreads per KV tile:
// wait(0) -> sync -> issue(kt+1) -> compute. exp2-domain softmax.
#define AP 68
#define ATT_SMEM (384 * AP * 4)        // Qs/Ps 128 + Ks 2x64 + Vs 2x64 rows

__global__ __launch_bounds__(256, 2) void attn_mma(
    const float* __restrict__ q, const float* __restrict__ k,
    const float* __restrict__ vT, float* __restrict__ out)
{
    extern __shared__ float sm[];
    const int bh = blockIdx.y, qt = blockIdx.x;
    const float* qb  = q  + (size_t)bh * Nv * Dv;
    const float* kb  = k  + (size_t)bh * Nv * Dv;
    const float* vTb = vT + (size_t)bh * Dv * Nv;
    const int tid = threadIdx.x, l = tid & 31, w = tid >> 5;
    const int wbase = w * 16;

    const uint32_t Qu = smem_u32(sm);
    uint32_t Ku[2], Vu[2];
    Ku[0] = Qu + 128 * AP * 4;  Ku[1] = Qu + 192 * AP * 4;
    Vu[0] = Qu + 256 * AP * 4;  Vu[1] = Qu + 320 * AP * 4;

    // lane ldmatrix offsets (floats)
    const int qoff = (wbase + (l & 15)) * AP + ((l >> 4) & 1) * 4;
    int koff[4];
#pragma unroll
    for (int p = 0; p < 4; p++)
        koff[p] = (p * 16 + ((l >> 4) << 3) + (l & 7)) * AP + ((l >> 3) & 1) * 4;

    // K/V tile load: 64 rows x 64 cols = 1024 chunks -> 4 per thread per operand
    auto issue_kv = [&](int kt) {
        const int slot = kt & 1;
#pragma unroll
        for (int j = 0; j < 4; j++) {
            int c = tid + 256 * j;
            int row = c >> 4, ks = (c & 15) * 4;
            cpa16(Ku[slot] + (uint32_t)(row * AP + ks) * 4,
                  kb + (size_t)(kt * 64 + row) * 64 + ks);
            cpa16(Vu[slot] + (uint32_t)(row * AP + ks) * 4,
                  vTb + (size_t)row * Nv + kt * 64 + ks);
        }
    };

    // prologue: Q tile 128x64 = 2048 chunks -> 8 per thread
    {
        const float* qp = qb + (size_t)qt * 128 * 64;
#pragma unroll
        for (int j = 0; j < 8; j++) {
            int c = tid + 256 * j;
            int row = c >> 4, ks = (c & 15) * 4;
            cpa16(Qu + (uint32_t)(row * AP + ks) * 4, qp + (size_t)row * 64 + ks);
        }
        CP_COMMIT();
        issue_kv(0); CP_COMMIT();
    }

    float o[8][4];
#pragma unroll
    for (int ni = 0; ni < 8; ni++)
#pragma unroll
        for (int e = 0; e < 4; e++) o[ni][e] = 0.f;
    float m0 = -1e30f, m1 = -1e30f, l0 = 0.f, l1 = 0.f;

    // hoist Q fragments (warp-private rows -> no cross-warp hazard with P reuse)
    uint32_t qa[8][4];
    CP_WAIT(1);                 // Q arrived (KV0 may still be in flight)
    __syncthreads();
#pragma unroll
    for (int ks = 0; ks < 8; ks++)
        LDSM4(qa[ks][0], qa[ks][1], qa[ks][2], qa[ks][3],
              Qu + (uint32_t)(qoff + ks * 8) * 4);
    __syncwarp();

    const int NT = Nv / 64;     // 32
    for (int kt = 0; kt < NT; kt++) {
        CP_WAIT(0);             // KV(kt) resident
        __syncthreads();        // all warps done with previous tile's smem
        if (kt + 1 < NT) { issue_kv(kt + 1); CP_COMMIT(); }

        const int slot = kt & 1;
        // S = Q K^T : per warp 16x64
        float s[8][4];
#pragma unroll
        for (int ni = 0; ni < 8; ni++)
#pragma unroll
            for (int e = 0; e < 4; e++) s[ni][e] = 0.f;
#pragma unroll
        for (int ks = 0; ks < 8; ks++) {
            const int k0 = ks * 8;
            uint32_t b[8][2];
#pragma unroll
            for (int p = 0; p < 4; p++)
                LDSM4(b[2*p][0], b[2*p][1], b[2*p+1][0], b[2*p+1][1],
                      Ku[slot] + (uint32_t)(koff[p] + k0) * 4);
#pragma unroll
            for (int ni = 0; ni < 8; ni++) MMA_TF32(s[ni], qa[ks], b[ni]);
        }

        // online softmax in exp2 domain (rows l>>2, l>>2 + 8)
        float mx0 = -1e30f, mx1 = -1e30f;
#pragma unroll
        for (int ni = 0; ni < 8; ni++) {
            mx0 = fmaxf(mx0, fmaxf(s[ni][0], s[ni][1]));
            mx1 = fmaxf(mx1, fmaxf(s[ni][2], s[ni][3]));
        }
        mx0 = fmaxf(mx0, __shfl_xor_sync(0xffffffffu, mx0, 1));
        mx0 = fmaxf(mx0, __shfl_xor_sync(0xffffffffu, mx0, 2));
        mx1 = fmaxf(mx1, __shfl_xor_sync(0xffffffffu, mx1, 1));
        mx1 = fmaxf(mx1, __shfl_xor_sync(0xffffffffu, mx1, 2));

        const float nm0 = fmaxf(m0, mx0), nm1 = fmaxf(m1, mx1);
        const float al0 = exp2f(m0 - nm0), al1 = exp2f(m1 - nm1);
        float rs0 = 0.f, rs1 = 0.f;
#pragma unroll
        for (int ni = 0; ni < 8; ni++) {
            s[ni][0] = exp2f(s[ni][0] - nm0); rs0 += s[ni][0];
            s[ni][1] = exp2f(s[ni][1] - nm0); rs0 += s[ni][1];
            s[ni][2] = exp2f(s[ni][2] - nm1); rs1 += s[ni][2];
            s[ni][3] = exp2f(s[ni][3] - nm1); rs1 += s[ni][3];
        }
        rs0 += __shfl_xor_sync(0xffffffffu, rs0, 1);
        rs0 += __shfl_xor_sync(0xffffffffu, rs0, 2);
        rs1 += __shfl_xor_sync(0xffffffffu, rs1, 1);
        rs1 += __shfl_xor_sync(0xffffffffu, rs1, 2);
        l0 = l0 * al0 + rs0; m0 = nm0;
        l1 = l1 * al1 + rs1; m1 = nm1;
#pragma unroll
        for (int ni = 0; ni < 8; ni++) {
            o[ni][0] *= al0; o[ni][1] *= al0;
            o[ni][2] *= al1; o[ni][3] *= al1;
        }

        // P (tf32) -> warp-private rows of the Q/P region
        const int pr = wbase + (l >> 2), pc = (l & 3) * 2;
        float* Ps = sm;
        __syncwarp();
#pragma unroll
        for (int ni = 0; ni < 8; ni++) {
            uint2 p0, p1;
            p0.x = tf32r(s[ni][0]); p0.y = tf32r(s[ni][1]);
            p1.x = tf32r(s[ni][2]); p1.y = tf32r(s[ni][3]);
            *(uint2*)(Ps + pr * AP + ni * 8 + pc) = p0;
            *(uint2*)(Ps + (pr + 8) * AP + ni * 8 + pc) = p1;
        }
        __syncwarp();

        // O += P V
#pragma unroll
        for (int ks = 0; ks < 8; ks++) {
            const int k0 = ks * 8;
            uint32_t a[4], b[8][2];
            LDSM4(a[0], a[1], a[2], a[3], Qu + (uint32_t)(qoff + k0) * 4);
#pragma unroll
            for (int p = 0; p < 4; p++)
                LDSM4(b[2*p][0], b[2*p][1], b[2*p+1][0], b[2*p+1][1],
                      Vu[slot] + (uint32_t)(koff[p] + k0) * 4);
#pragma unroll
            for (int ni = 0; ni < 8; ni++) MMA_TF32(o[ni], a, b[ni]);
        }
    }

    // epilogue -> att [B,N,C], tf32-rounded (it feeds the proj GEMM raw)
    const int b_ = bh >> 4, h_ = bh & 15;
    const float i0 = 1.f / l0, i1 = 1.f / l1;
    const int n0 = qt * 128 + wbase + (l >> 2);
#pragma unroll
    for (int ni = 0; ni < 8; ni++) {
        const int col = h_ * 64 + ni * 8 + (l & 3) * 2;
        uint2 v0, v1;
        v0.x = tf32r(o[ni][0] * i0); v0.y = tf32r(o[ni][1] * i0);
        v1.x = tf32r(o[ni][2] * i1); v1.y = tf32r(o[ni][3] * i1);
        *(uint2*)(out + (size_t)(b_ * Nv + n0) * Cv + col) = v0;
        *(uint2*)(out + (size_t)(b_ * Nv + n0 + 8) * Cv + col) = v1;
    }
}

// ---------------- launch -----------------------------------------------------
extern "C" void kernel_launch(void* const* d_in, const int* in_sizes, int n_in,
                              void* d_out, int out_size)
{
    const float* x        = (const float*)d_in[0];
    const float* rope_cos = (const float*)d_in[1];
    const float* rope_sin = (const float*)d_in[2];
    const float* w_qkv    = (const float*)d_in[3];
    const float* w_proj   = (const float*)d_in[4];
    const float* b_proj   = (const float*)d_in[5];
    float* out = (float*)d_out;

    float *qkv, *q, *k, *vT, *att, *xr, *wqr, *wpr;
    cudaGetSymbolAddress((void**)&qkv, g_qkv);
    cudaGetSymbolAddress((void**)&q,   g_q);
    cudaGetSymbolAddress((void**)&k,   g_k);
    cudaGetSymbolAddress((void**)&vT,  g_vT);
    cudaGetSymbolAddress((void**)&att, g_att);
    cudaGetSymbolAddress((void**)&xr,  g_xr);
    cudaGetSymbolAddress((void**)&wqr, g_wqkvr);
    cudaGetSymbolAddress((void**)&wpr, g_wprojr);

    cudaFuncSetAttribute(gemm_mma, cudaFuncAttributeMaxDynamicSharedMemorySize, GEMM_SMEM);
    cudaFuncSetAttribute(attn_mma, cudaFuncAttributeMaxDynamicSharedMemorySize, ATT_SMEM);

    // 0) pre-round inputs to tf32-exact fp32 (lets all hot loops cp.async raw)
    round_tf32<<<(Mv * Cv / 4 + 255) / 256, 256>>>((const float4*)x, (float4*)xr, Mv * Cv / 4);
    round_tf32<<<(F3 * Cv / 4 + 255) / 256, 256>>>((const float4*)w_qkv, (float4*)wqr, F3 * Cv / 4);
    round_tf32<<<(Cv * Cv / 4 + 255) / 256, 256>>>((const float4*)w_proj, (float4*)wpr, Cv * Cv / 4);

    // 1) QKV GEMM: [8192,1024] x [3072,1024]^T -> [8192,3072]
    gemm_mma<<<dim3(F3 / 128, Mv / 128), 256, GEMM_SMEM>>>(xr, wqr, qkv, F3, Cv, nullptr);

    // 2) RoPE + transpose (q,k rounded + exp2-domain scale; v rounded + transposed)
    rope_transpose<<<(Bv * Hv * Nv * 32) / 256, 256>>>(qkv, q, k, vT, rope_cos, rope_sin);

    // 3) Flash attention (tensor cores, Br=128, single-sync pipeline)
    attn_mma<<<dim3(Nv / 128, Bv * Hv), 256, ATT_SMEM>>>(q, k, vT, att);

    // 4) projection + bias: [8192,1024] x [1024,1024]^T -> d_out
    gemm_mma<<<dim3(Cv / 128, Mv / 128), 256, GEMM_SMEM>>>(att, wpr, out, Cv, Cv, b_proj);
}